// round 2
// baseline (speedup 1.0000x reference)
#include <cuda_runtime.h>
#include <mma.h>
#include <cstdint>
#include <math.h>

using namespace nvcuda;

// Problem constants
constexpr int Bb = 2, Ss = 2048, Ee = 4096, Hh = 16, Dd = 256, Rr = 64;
constexpr int Mtot = Bb * Ss;                  // 4096
constexpr size_t QK_ELEMS = (size_t)Bb * Hh * Ss * Dd;   // 16777216

// GEMM tiling
constexpr int BM = 128, BN = 128, BK = 32;
constexpr int ASTR = BK + 8;    // 40  (shared A/B row stride)
constexpr int CSTR = BN + 4;    // 132 (shared C row stride)
constexpr size_t SMEM_FLOATS = (2 * BM * ASTR) > (BM * CSTR) ? (size_t)(2 * BM * ASTR) : (size_t)(BM * CSTR);
constexpr size_t SMEM_BYTES = SMEM_FLOATS * sizeof(float);   // 67584

// Scratch: normalized x (no cudaMalloc allowed)
__device__ float g_xnorm[(size_t)Mtot * Ee];

// ---------------------------------------------------------------------------
// LayerNorm: one block per row of 4096
// ---------------------------------------------------------------------------
__global__ void __launch_bounds__(256) ln_kernel(const float* __restrict__ x,
                                                 const float* __restrict__ w,
                                                 const float* __restrict__ b) {
    int row = blockIdx.x;
    int tid = threadIdx.x;
    const float4* xr = reinterpret_cast<const float4*>(x + (size_t)row * Ee);

    float4 v[4];
    float sum = 0.f, ssq = 0.f;
#pragma unroll
    for (int j = 0; j < 4; j++) {
        v[j] = xr[tid + j * 256];
        sum += v[j].x + v[j].y + v[j].z + v[j].w;
        ssq += v[j].x * v[j].x + v[j].y * v[j].y + v[j].z * v[j].z + v[j].w * v[j].w;
    }
    // block reduce (sum, ssq)
    __shared__ float s_sum[8], s_ssq[8];
#pragma unroll
    for (int o = 16; o; o >>= 1) {
        sum += __shfl_xor_sync(~0u, sum, o);
        ssq += __shfl_xor_sync(~0u, ssq, o);
    }
    if ((tid & 31) == 0) { s_sum[tid >> 5] = sum; s_ssq[tid >> 5] = ssq; }
    __syncthreads();
    if (tid < 32) {
        float ts = (tid < 8) ? s_sum[tid] : 0.f;
        float tq = (tid < 8) ? s_ssq[tid] : 0.f;
#pragma unroll
        for (int o = 4; o; o >>= 1) {
            ts += __shfl_xor_sync(~0u, ts, o);
            tq += __shfl_xor_sync(~0u, tq, o);
        }
        if (tid == 0) { s_sum[0] = ts; s_ssq[0] = tq; }
    }
    __syncthreads();
    float mean = s_sum[0] * (1.0f / Ee);
    float var = s_ssq[0] * (1.0f / Ee) - mean * mean;
    float rstd = rsqrtf(var + 1e-5f);

    const float4* wr = reinterpret_cast<const float4*>(w);
    const float4* br = reinterpret_cast<const float4*>(b);
    float4* outr = reinterpret_cast<float4*>(g_xnorm + (size_t)row * Ee);
#pragma unroll
    for (int j = 0; j < 4; j++) {
        int c = tid + j * 256;
        float4 wv = wr[c], bv = br[c], o;
        o.x = (v[j].x - mean) * rstd * wv.x + bv.x;
        o.y = (v[j].y - mean) * rstd * wv.y + bv.y;
        o.z = (v[j].z - mean) * rstd * wv.z + bv.z;
        o.w = (v[j].w - mean) * rstd * wv.w + bv.w;
        outr[c] = o;
    }
}

// ---------------------------------------------------------------------------
// Shared GEMM mainloop: C[m][n] = sum_k A[m][k]*Bmat[n][k]  (NT, tf32 wmma)
// ---------------------------------------------------------------------------
using AccFrag = wmma::fragment<wmma::accumulator, 16, 16, 8, float>;

template <int LDA, int KTOT>
__device__ __forceinline__ void gemm_main(const float* __restrict__ A,
                                          const float* __restrict__ Bmat,
                                          int m0, int n0,
                                          float* As, float* Bs,
                                          AccFrag acc[4][2]) {
    int tid = threadIdx.x;
    int warp = tid >> 5;
    int wm = warp & 1;        // 2 warps along M (64 rows each)
    int wn = warp >> 1;       // 4 warps along N (32 cols each)

    for (int k0 = 0; k0 < KTOT; k0 += BK) {
#pragma unroll
        for (int l = 0; l < 4; l++) {
            int idx = tid + l * 256;         // 0..1023
            int r = idx >> 3;                // 0..127
            int c = (idx & 7) << 2;          // 0..28 step 4
            float4 va = *reinterpret_cast<const float4*>(A + (size_t)(m0 + r) * LDA + k0 + c);
            float4 vb = *reinterpret_cast<const float4*>(Bmat + (size_t)(n0 + r) * LDA + k0 + c);
            float* ad = As + r * ASTR + c;
            ad[0] = wmma::__float_to_tf32(va.x); ad[1] = wmma::__float_to_tf32(va.y);
            ad[2] = wmma::__float_to_tf32(va.z); ad[3] = wmma::__float_to_tf32(va.w);
            float* bd = Bs + r * ASTR + c;
            bd[0] = wmma::__float_to_tf32(vb.x); bd[1] = wmma::__float_to_tf32(vb.y);
            bd[2] = wmma::__float_to_tf32(vb.z); bd[3] = wmma::__float_to_tf32(vb.w);
        }
        __syncthreads();
#pragma unroll
        for (int kk = 0; kk < BK; kk += 8) {
            wmma::fragment<wmma::matrix_a, 16, 16, 8, wmma::precision::tf32, wmma::row_major> af[4];
            wmma::fragment<wmma::matrix_b, 16, 16, 8, wmma::precision::tf32, wmma::col_major> bf[2];
#pragma unroll
            for (int i = 0; i < 4; i++)
                wmma::load_matrix_sync(af[i], As + (wm * 64 + i * 16) * ASTR + kk, ASTR);
#pragma unroll
            for (int j = 0; j < 2; j++)
                wmma::load_matrix_sync(bf[j], Bs + (wn * 32 + j * 16) * ASTR + kk, ASTR);
#pragma unroll
            for (int i = 0; i < 4; i++)
#pragma unroll
                for (int j = 0; j < 2; j++)
                    wmma::mma_sync(acc[i][j], af[i], bf[j], acc[i][j]);
        }
        __syncthreads();
    }
}

__device__ __forceinline__ void store_acc_to_smem(float* Cs, AccFrag acc[4][2]) {
    int warp = threadIdx.x >> 5;
    int wm = warp & 1, wn = warp >> 1;
#pragma unroll
    for (int i = 0; i < 4; i++)
#pragma unroll
        for (int j = 0; j < 2; j++)
            wmma::store_matrix_sync(Cs + (wm * 64 + i * 16) * CSTR + wn * 32 + j * 16,
                                    acc[i][j], CSTR, wmma::mem_row_major);
}

// ---------------------------------------------------------------------------
// Projection GEMM + bias + RoPE + transposed write to (B,H,S,D)
// ---------------------------------------------------------------------------
__global__ void __launch_bounds__(256, 1) proj_gemm_kernel(
    const float* __restrict__ W,        // [E,E] row = output feature
    const float* __restrict__ bias,     // [E]
    const float* __restrict__ embed,    // [S,64]  (sin[0:32] | cos[32:64])
    const int* __restrict__ posids,     // [B*S]
    float* __restrict__ outp)           // [B,H,S,D]
{
    extern __shared__ float smem[];
    float* As = smem;
    float* Bs = smem + BM * ASTR;
    int m0 = blockIdx.y * BM;
    int n0 = blockIdx.x * BN;

    AccFrag acc[4][2];
#pragma unroll
    for (int i = 0; i < 4; i++)
#pragma unroll
        for (int j = 0; j < 2; j++)
            wmma::fill_fragment(acc[i][j], 0.f);

    gemm_main<Ee, Ee>(g_xnorm, W, m0, n0, As, Bs, acc);

    float* Cs = smem;
    store_acc_to_smem(Cs, acc);
    __syncthreads();

    // Epilogue: bias + RoPE on paired columns, write transposed
    for (int it = threadIdx.x; it < BM * (BN / 2); it += 256) {
        int r = it >> 6;            // 0..127
        int pc = it & 63;           // pair column
        int c = pc << 1;
        int m = m0 + r, f = n0 + c;
        int b = m >> 11, s = m & 2047;
        int h = f >> 8, d = f & 255;
        float v0 = Cs[r * CSTR + c] + bias[f];
        float v1 = Cs[r * CSTR + c + 1] + bias[f + 1];
        if (d < Rr) {
            int pos = posids[m];
            int i2 = d >> 1;
            float sn = embed[pos * Rr + i2];
            float co = embed[pos * Rr + 32 + i2];
            float o0 = v0 * co - v1 * sn;
            float o1 = v1 * co + v0 * sn;
            v0 = o0; v1 = o1;
        }
        float2* dst = reinterpret_cast<float2*>(
            outp + (((size_t)(b * Hh + h) * Ss + s) * Dd + d));
        *dst = make_float2(v0, v1);
    }
}

// ---------------------------------------------------------------------------
// Scores GEMM: scores[bh][q][k] = (Q[bh,q,:] . K[bh,k,:]) / 16
// Skips strictly-upper causal tiles.
// ---------------------------------------------------------------------------
__global__ void __launch_bounds__(256, 1) scores_kernel(
    const float* __restrict__ Q,   // [B*H, S, D]
    const float* __restrict__ Kv,  // [B*H, S, D]
    float* __restrict__ attn)      // [B*H, S, S] (raw scores for now)
{
    int kt = blockIdx.x, qt = blockIdx.y, bh = blockIdx.z;
    if (kt > qt) return;   // fully masked tile

    extern __shared__ float smem[];
    float* As = smem;
    float* Bs = smem + BM * ASTR;
    int m0 = qt * BM, n0 = kt * BN;
    const float* A = Q + (size_t)bh * Ss * Dd;
    const float* Bmat = Kv + (size_t)bh * Ss * Dd;

    AccFrag acc[4][2];
#pragma unroll
    for (int i = 0; i < 4; i++)
#pragma unroll
        for (int j = 0; j < 2; j++)
            wmma::fill_fragment(acc[i][j], 0.f);

    gemm_main<Dd, Dd>(A, Bmat, m0, n0, As, Bs, acc);

    float* Cs = smem;
    store_acc_to_smem(Cs, acc);
    __syncthreads();

    float* out_base = attn + (size_t)bh * Ss * Ss;
    for (int it = threadIdx.x; it < BM * BN; it += 256) {
        int r = it >> 7, c = it & 127;
        out_base[(size_t)(m0 + r) * Ss + n0 + c] = Cs[r * CSTR + c] * 0.0625f;
    }
}

// ---------------------------------------------------------------------------
// In-place masked softmax over each row of [B*H*S, S]
// ---------------------------------------------------------------------------
__global__ void __launch_bounds__(256) softmax_kernel(float* __restrict__ attn) {
    int row = blockIdx.x;          // bh*2048 + q
    int q = row & 2047;
    int nv = q + 1;
    float* rowp = attn + (size_t)row * Ss;
    int tid = threadIdx.x;

    float vals[8];
    float mx = -INFINITY;
#pragma unroll
    for (int j = 0; j < 8; j++) {
        int k = tid + j * 256;
        float v = (k < nv) ? rowp[k] : -INFINITY;
        vals[j] = v;
        mx = fmaxf(mx, v);
    }
    __shared__ float sh[8];
#pragma unroll
    for (int o = 16; o; o >>= 1) mx = fmaxf(mx, __shfl_xor_sync(~0u, mx, o));
    if ((tid & 31) == 0) sh[tid >> 5] = mx;
    __syncthreads();
    if (tid < 32) {
        float t = (tid < 8) ? sh[tid] : -INFINITY;
#pragma unroll
        for (int o = 4; o; o >>= 1) t = fmaxf(t, __shfl_xor_sync(~0u, t, o));
        if (tid == 0) sh[0] = t;
    }
    __syncthreads();
    float M = sh[0];
    __syncthreads();

    float sum = 0.f;
#pragma unroll
    for (int j = 0; j < 8; j++) {
        int k = tid + j * 256;
        float e = (k < nv) ? expf(vals[j] - M) : 0.f;
        vals[j] = e;
        sum += e;
    }
#pragma unroll
    for (int o = 16; o; o >>= 1) sum += __shfl_xor_sync(~0u, sum, o);
    if ((tid & 31) == 0) sh[tid >> 5] = sum;
    __syncthreads();
    if (tid < 32) {
        float t = (tid < 8) ? sh[tid] : 0.f;
#pragma unroll
        for (int o = 4; o; o >>= 1) t += __shfl_xor_sync(~0u, t, o);
        if (tid == 0) sh[0] = t;
    }
    __syncthreads();
    float inv = 1.0f / sh[0];
#pragma unroll
    for (int j = 0; j < 8; j++) {
        int k = tid + j * 256;
        rowp[k] = vals[j] * inv;   // zeros in masked region (clears poison)
    }
}

// ---------------------------------------------------------------------------
extern "C" void kernel_launch(void* const* d_in, const int* in_sizes, int n_in,
                              void* d_out, int out_size) {
    const float* x     = (const float*)d_in[0];
    const float* q_w   = (const float*)d_in[1];
    const float* q_b   = (const float*)d_in[2];
    const float* k_w   = (const float*)d_in[3];
    const float* k_b   = (const float*)d_in[4];
    const float* ln_w  = (const float*)d_in[5];
    const float* ln_b  = (const float*)d_in[6];
    const float* embed = (const float*)d_in[7];
    const int*   pos   = (const int*)d_in[8];

    float* out   = (float*)d_out;
    float* q_out = out;
    float* k_out = out + QK_ELEMS;
    float* attn  = out + 2 * QK_ELEMS;

    cudaFuncSetAttribute(proj_gemm_kernel, cudaFuncAttributeMaxDynamicSharedMemorySize, (int)SMEM_BYTES);
    cudaFuncSetAttribute(scores_kernel,   cudaFuncAttributeMaxDynamicSharedMemorySize, (int)SMEM_BYTES);

    ln_kernel<<<Mtot, 256>>>(x, ln_w, ln_b);

    dim3 g1(Ee / BN, Mtot / BM);            // (32, 32)
    proj_gemm_kernel<<<g1, 256, SMEM_BYTES>>>(q_w, q_b, embed, pos, q_out);
    proj_gemm_kernel<<<g1, 256, SMEM_BYTES>>>(k_w, k_b, embed, pos, k_out);

    dim3 g2(Ss / BN, Ss / BM, Bb * Hh);     // (16, 16, 32)
    scores_kernel<<<g2, 256, SMEM_BYTES>>>(q_out, k_out, attn);

    softmax_kernel<<<Bb * Hh * Ss, 256>>>(attn);
}

// round 5
// speedup vs baseline: 1.2449x; 1.2449x over previous
#include <cuda_runtime.h>
#include <mma.h>
#include <cstdint>
#include <math.h>

using namespace nvcuda;

// Problem constants
constexpr int Bb = 2, Ss = 2048, Ee = 4096, Hh = 16, Dd = 256, Rr = 64;
constexpr int Mtot = Bb * Ss;                  // 4096
constexpr size_t QK_ELEMS = (size_t)Bb * Hh * Ss * Dd;   // 16777216

// GEMM tiling
constexpr int BM = 128, BN = 128, BK = 32;
constexpr int ASTR = BK + 8;            // 40 floats = 160 bytes per row
constexpr uint32_t STAGE_A_BYTES = 128 * ASTR * 4;       // 20480
constexpr uint32_t STAGE_BYTES = 2 * STAGE_A_BYTES;      // 40960 (A+B)
constexpr int NSTAGE = 3;
constexpr int CSTR = BN + 4;            // 132
constexpr uint32_t GEMM_SMEM = NSTAGE * STAGE_BYTES;     // 122880 (> 128*132*4=67584 for Cs reuse)

// Scratch (__device__ globals; no allocs allowed)
__device__ float g_xnorm[(size_t)Mtot * Ee];     // tf32-rounded LN output
__device__ float g_wq[(size_t)Ee * Ee];          // tf32-rounded weights
__device__ float g_wk[(size_t)Ee * Ee];
__device__ float g_qr[QK_ELEMS];                 // tf32-rounded q/k for scores
__device__ float g_kr[QK_ELEMS];

__device__ __forceinline__ uint32_t smem_u32(const void* p) {
    uint32_t a;
    asm("{ .reg .u64 t; cvta.to.shared.u64 t, %1; cvt.u32.u64 %0, t; }" : "=r"(a) : "l"(p));
    return a;
}
__device__ __forceinline__ void cp16(uint32_t dst, const void* src) {
    asm volatile("cp.async.cg.shared.global [%0], [%1], 16;" :: "r"(dst), "l"(src));
}
#define CP_COMMIT() asm volatile("cp.async.commit_group;" ::: "memory")
#define CP_WAIT2()  asm volatile("cp.async.wait_group 2;" ::: "memory")

// ---------------------------------------------------------------------------
// LayerNorm (writes tf32-rounded output)
// ---------------------------------------------------------------------------
__global__ void __launch_bounds__(256) ln_kernel(const float* __restrict__ x,
                                                 const float* __restrict__ w,
                                                 const float* __restrict__ b) {
    int row = blockIdx.x;
    int tid = threadIdx.x;
    const float4* xr = reinterpret_cast<const float4*>(x + (size_t)row * Ee);

    float4 v[4];
    float sum = 0.f, ssq = 0.f;
#pragma unroll
    for (int j = 0; j < 4; j++) {
        v[j] = xr[tid + j * 256];
        sum += v[j].x + v[j].y + v[j].z + v[j].w;
        ssq += v[j].x * v[j].x + v[j].y * v[j].y + v[j].z * v[j].z + v[j].w * v[j].w;
    }
    __shared__ float s_sum[8], s_ssq[8];
#pragma unroll
    for (int o = 16; o; o >>= 1) {
        sum += __shfl_xor_sync(~0u, sum, o);
        ssq += __shfl_xor_sync(~0u, ssq, o);
    }
    if ((tid & 31) == 0) { s_sum[tid >> 5] = sum; s_ssq[tid >> 5] = ssq; }
    __syncthreads();
    if (tid < 32) {
        float ts = (tid < 8) ? s_sum[tid] : 0.f;
        float tq = (tid < 8) ? s_ssq[tid] : 0.f;
#pragma unroll
        for (int o = 4; o; o >>= 1) {
            ts += __shfl_xor_sync(~0u, ts, o);
            tq += __shfl_xor_sync(~0u, tq, o);
        }
        if (tid == 0) { s_sum[0] = ts; s_ssq[0] = tq; }
    }
    __syncthreads();
    float mean = s_sum[0] * (1.0f / Ee);
    float var = s_ssq[0] * (1.0f / Ee) - mean * mean;
    float rstd = rsqrtf(var + 1e-5f);

    const float4* wr = reinterpret_cast<const float4*>(w);
    const float4* br = reinterpret_cast<const float4*>(b);
    float4* outr = reinterpret_cast<float4*>(g_xnorm + (size_t)row * Ee);
#pragma unroll
    for (int j = 0; j < 4; j++) {
        int c = tid + j * 256;
        float4 wv = wr[c], bv = br[c], o;
        o.x = wmma::__float_to_tf32((v[j].x - mean) * rstd * wv.x + bv.x);
        o.y = wmma::__float_to_tf32((v[j].y - mean) * rstd * wv.y + bv.y);
        o.z = wmma::__float_to_tf32((v[j].z - mean) * rstd * wv.z + bv.z);
        o.w = wmma::__float_to_tf32((v[j].w - mean) * rstd * wv.w + bv.w);
        outr[c] = o;
    }
}

// ---------------------------------------------------------------------------
// Weight pre-rounding to tf32
// ---------------------------------------------------------------------------
__global__ void __launch_bounds__(256) wconv_kernel(const float* __restrict__ wq,
                                                    const float* __restrict__ wk) {
    const float* src = blockIdx.y ? wk : wq;
    float* dst = blockIdx.y ? g_wk : g_wq;
    size_t i = ((size_t)blockIdx.x * 256 + threadIdx.x) * 4;
    float4 v = *reinterpret_cast<const float4*>(src + i);
    v.x = wmma::__float_to_tf32(v.x);
    v.y = wmma::__float_to_tf32(v.y);
    v.z = wmma::__float_to_tf32(v.z);
    v.w = wmma::__float_to_tf32(v.w);
    *reinterpret_cast<float4*>(dst + i) = v;
}

// ---------------------------------------------------------------------------
// Pipelined tf32 wmma GEMM mainloop (NT): C = A * B^T over NCHUNK*32 K-dims.
// A/B pre-rounded to tf32. 3-stage cp.async double buffering.
// ---------------------------------------------------------------------------
using AccFrag = wmma::fragment<wmma::accumulator, 16, 16, 8, float>;

__device__ __forceinline__ void load_chunk(uint32_t sb, const char* Ab, const char* Bbp,
                                           size_t ldab, int kc, int buf, int tid) {
    uint32_t stA = sb + buf * STAGE_BYTES;
    uint32_t stB = stA + STAGE_A_BYTES;
    const char* Ap = Ab + (size_t)kc * (BK * 4);
    const char* Bp = Bbp + (size_t)kc * (BK * 4);
#pragma unroll
    for (int l = 0; l < 4; l++) {
        int idx = tid + l * 256;         // 0..1023
        int r = idx >> 3;                // 0..127
        int cb = (idx & 7) << 4;         // 0..112 step 16
        cp16(stA + r * (ASTR * 4) + cb, Ap + (size_t)r * ldab + cb);
        cp16(stB + r * (ASTR * 4) + cb, Bp + (size_t)r * ldab + cb);
    }
}

template <int NCHUNK>
__device__ __forceinline__ void gemm_pipe(const char* Ab, const char* Bbp, size_t ldab,
                                          char* smem, AccFrag acc[4][2]) {
    uint32_t sb = smem_u32(smem);
    int tid = threadIdx.x;
    int warp = tid >> 5;
    int wm = warp & 1;
    int wn = warp >> 1;

    load_chunk(sb, Ab, Bbp, ldab, 0, 0, tid);
    CP_COMMIT();
    if (NCHUNK > 1) load_chunk(sb, Ab, Bbp, ldab, 1, 1, tid);
    CP_COMMIT();

    for (int k = 0; k < NCHUNK; k++) {
        if (k + 2 < NCHUNK) load_chunk(sb, Ab, Bbp, ldab, k + 2, (k + 2) % NSTAGE, tid);
        CP_COMMIT();
        CP_WAIT2();
        __syncthreads();

        float* As = reinterpret_cast<float*>(smem + (k % NSTAGE) * STAGE_BYTES);
        float* Bs = As + 128 * ASTR;
#pragma unroll
        for (int kk = 0; kk < BK; kk += 8) {
            wmma::fragment<wmma::matrix_a, 16, 16, 8, wmma::precision::tf32, wmma::row_major> af[4];
            wmma::fragment<wmma::matrix_b, 16, 16, 8, wmma::precision::tf32, wmma::col_major> bf[2];
#pragma unroll
            for (int i = 0; i < 4; i++)
                wmma::load_matrix_sync(af[i], As + (wm * 64 + i * 16) * ASTR + kk, ASTR);
#pragma unroll
            for (int j = 0; j < 2; j++)
                wmma::load_matrix_sync(bf[j], Bs + (wn * 32 + j * 16) * ASTR + kk, ASTR);
#pragma unroll
            for (int i = 0; i < 4; i++)
#pragma unroll
                for (int j = 0; j < 2; j++)
                    wmma::mma_sync(acc[i][j], af[i], bf[j], acc[i][j]);
        }
        __syncthreads();
    }
}

__device__ __forceinline__ void store_acc(float* Cs, AccFrag acc[4][2]) {
    int warp = threadIdx.x >> 5;
    int wm = warp & 1, wn = warp >> 1;
#pragma unroll
    for (int i = 0; i < 4; i++)
#pragma unroll
        for (int j = 0; j < 2; j++)
            wmma::store_matrix_sync(Cs + (wm * 64 + i * 16) * CSTR + wn * 32 + j * 16,
                                    acc[i][j], CSTR, wmma::mem_row_major);
}

// ---------------------------------------------------------------------------
// Projection GEMM + bias + RoPE, writes q/k (fp32) and tf32-rounded copies
// ---------------------------------------------------------------------------
__global__ void __launch_bounds__(256, 1) proj_cp_kernel(
    const float* __restrict__ bq, const float* __restrict__ bk,
    const float* __restrict__ embed, const int* __restrict__ posids,
    float* __restrict__ qout, float* __restrict__ kout)
{
    extern __shared__ __align__(128) char smem[];
    int z = blockIdx.z;
    const float* W    = z ? g_wk : g_wq;
    const float* bias = z ? bk : bq;
    float* outp       = z ? kout : qout;
    float* routp      = z ? g_kr : g_qr;
    const int m0 = blockIdx.x * BM;   // x fastest over M: consecutive CTAs share B-panel
    const int n0 = blockIdx.y * BN;

    AccFrag acc[4][2];
#pragma unroll
    for (int i = 0; i < 4; i++)
#pragma unroll
        for (int j = 0; j < 2; j++)
            wmma::fill_fragment(acc[i][j], 0.f);

    gemm_pipe<Ee / BK>(reinterpret_cast<const char*>(g_xnorm + (size_t)m0 * Ee),
                       reinterpret_cast<const char*>(W + (size_t)n0 * Ee),
                       (size_t)Ee * 4, smem, acc);

    float* Cs = reinterpret_cast<float*>(smem);
    store_acc(Cs, acc);
    __syncthreads();

    int tid = threadIdx.x;
#pragma unroll 4
    for (int i = 0; i < 32; i++) {
        int it = tid + i * 256;          // 0..8191
        int r = it >> 6;                 // 0..127
        int pc = it & 63;                // pair col
        int c = pc << 1;
        int m = m0 + r, f = n0 + c;
        float v0 = Cs[r * CSTR + c] + bias[f];
        float v1 = Cs[r * CSTR + c + 1] + bias[f + 1];
        int d = f & 255;
        if (d < Rr) {
            int pos = posids[m];
            int i2 = d >> 1;
            float sn = embed[pos * Rr + i2];
            float co = embed[pos * Rr + 32 + i2];
            float o0 = v0 * co - v1 * sn;
            float o1 = v1 * co + v0 * sn;
            v0 = o0; v1 = o1;
        }
        int b_ = m >> 11, s_ = m & 2047, h_ = f >> 8;
        size_t off = ((size_t)(b_ * Hh + h_) * Ss + s_) * Dd + d;
        *reinterpret_cast<float2*>(outp + off) = make_float2(v0, v1);
        *reinterpret_cast<float2*>(routp + off) =
            make_float2(wmma::__float_to_tf32(v0), wmma::__float_to_tf32(v1));
    }
}

// ---------------------------------------------------------------------------
// Scores GEMM (pipelined): scores = Qr.Kr^T / 16, causal tile skip
// ---------------------------------------------------------------------------
__global__ void __launch_bounds__(256, 1) scores_cp_kernel(float* __restrict__ attn)
{
    int kt = blockIdx.x, qt = blockIdx.y, bh = blockIdx.z;
    if (kt > qt) return;

    extern __shared__ __align__(128) char smem[];
    int m0 = qt * BM, n0 = kt * BN;
    const float* Q = g_qr + (size_t)bh * Ss * Dd;
    const float* Kv = g_kr + (size_t)bh * Ss * Dd;

    AccFrag acc[4][2];
#pragma unroll
    for (int i = 0; i < 4; i++)
#pragma unroll
        for (int j = 0; j < 2; j++)
            wmma::fill_fragment(acc[i][j], 0.f);

    gemm_pipe<Dd / BK>(reinterpret_cast<const char*>(Q + (size_t)m0 * Dd),
                       reinterpret_cast<const char*>(Kv + (size_t)n0 * Dd),
                       (size_t)Dd * 4, smem, acc);

    float* Cs = reinterpret_cast<float*>(smem);
    store_acc(Cs, acc);
    __syncthreads();

    float* out_base = attn + (size_t)bh * Ss * Ss;
    for (int it = threadIdx.x; it < BM * BN; it += 256) {
        int r = it >> 7, c = it & 127;
        out_base[(size_t)(m0 + r) * Ss + n0 + c] = Cs[r * CSTR + c] * 0.0625f;
    }
}

// ---------------------------------------------------------------------------
// In-place masked softmax
// ---------------------------------------------------------------------------
__global__ void __launch_bounds__(256) softmax_kernel(float* __restrict__ attn) {
    int row = blockIdx.x;
    int q = row & 2047;
    int nv = q + 1;
    float* rowp = attn + (size_t)row * Ss;
    int tid = threadIdx.x;

    float vals[8];
    float mx = -INFINITY;
#pragma unroll
    for (int j = 0; j < 8; j++) {
        int k = tid + j * 256;
        float v = (k < nv) ? rowp[k] : -INFINITY;
        vals[j] = v;
        mx = fmaxf(mx, v);
    }
    __shared__ float sh[8];
#pragma unroll
    for (int o = 16; o; o >>= 1) mx = fmaxf(mx, __shfl_xor_sync(~0u, mx, o));
    if ((tid & 31) == 0) sh[tid >> 5] = mx;
    __syncthreads();
    if (tid < 32) {
        float t = (tid < 8) ? sh[tid] : -INFINITY;
#pragma unroll
        for (int o = 4; o; o >>= 1) t = fmaxf(t, __shfl_xor_sync(~0u, t, o));
        if (tid == 0) sh[0] = t;
    }
    __syncthreads();
    float M = sh[0];
    __syncthreads();

    float sum = 0.f;
#pragma unroll
    for (int j = 0; j < 8; j++) {
        int k = tid + j * 256;
        float e = (k < nv) ? expf(vals[j] - M) : 0.f;
        vals[j] = e;
        sum += e;
    }
#pragma unroll
    for (int o = 16; o; o >>= 1) sum += __shfl_xor_sync(~0u, sum, o);
    if ((tid & 31) == 0) sh[tid >> 5] = sum;
    __syncthreads();
    if (tid < 32) {
        float t = (tid < 8) ? sh[tid] : 0.f;
#pragma unroll
        for (int o = 4; o; o >>= 1) t += __shfl_xor_sync(~0u, t, o);
        if (tid == 0) sh[0] = t;
    }
    __syncthreads();
    float inv = 1.0f / sh[0];
#pragma unroll
    for (int j = 0; j < 8; j++) {
        int k = tid + j * 256;
        rowp[k] = vals[j] * inv;
    }
}

// ---------------------------------------------------------------------------
extern "C" void kernel_launch(void* const* d_in, const int* in_sizes, int n_in,
                              void* d_out, int out_size) {
    const float* x     = (const float*)d_in[0];
    const float* q_w   = (const float*)d_in[1];
    const float* q_b   = (const float*)d_in[2];
    const float* k_w   = (const float*)d_in[3];
    const float* k_b   = (const float*)d_in[4];
    const float* ln_w  = (const float*)d_in[5];
    const float* ln_b  = (const float*)d_in[6];
    const float* embed = (const float*)d_in[7];
    const int*   pos   = (const int*)d_in[8];

    float* out   = (float*)d_out;
    float* q_out = out;
    float* k_out = out + QK_ELEMS;
    float* attn  = out + 2 * QK_ELEMS;

    cudaFuncSetAttribute(proj_cp_kernel, cudaFuncAttributeMaxDynamicSharedMemorySize, (int)GEMM_SMEM);
    cudaFuncSetAttribute(scores_cp_kernel, cudaFuncAttributeMaxDynamicSharedMemorySize, (int)GEMM_SMEM);

    ln_kernel<<<Mtot, 256>>>(x, ln_w, ln_b);

    dim3 gw((unsigned)(((size_t)Ee * Ee) / 1024), 2);   // 16384 x 2
    wconv_kernel<<<gw, 256>>>(q_w, k_w);

    dim3 gp(Mtot / BM, Ee / BN, 2);          // (32, 32, 2), x over M
    proj_cp_kernel<<<gp, 256, GEMM_SMEM>>>(q_b, k_b, embed, pos, q_out, k_out);

    dim3 g2(Ss / BN, Ss / BM, Bb * Hh);      // (16, 16, 32)
    scores_cp_kernel<<<g2, 256, GEMM_SMEM>>>(attn);

    softmax_kernel<<<Bb * Hh * Ss, 256>>>(attn);
}